// round 2
// baseline (speedup 1.0000x reference)
#include <cuda_runtime.h>
#include <cuda_fp16.h>
#include <cstdint>
#include <cstddef>

// out[h,n,m] = LeakyReLU_{0.2}( sum_d z0[n,d]*z1[m,d]*W[h,d] + bias[h] )
// N=M=1024, D=256, H=128, fp32 in/out.
//
// Engine: ldmatrix + mma.sync.m16n8k16 (arch-agnostic PTX; tcgen05 is rejected
// because the harness compiles at virtual arch compute_103 without 'a').
//
// CTA = (n-tile of 128) x (pair of heads h0,h0+1).
//   sB[hh] = fp16( z0[n0:n0+128,:] * W[h0+hh,:] )   (MMA operand A, rows = n)
//   sA     = fp16( z1[m0:m0+128,:] )                (MMA operand B, cols = m)
// MMA rows = n, cols = m  =>  each lane holds adjacent m-pairs => float2 stores.

#define NT 512

static constexpr int ROW_BYTES = 528;            // 256 fp16 + 16B pad (conflict-free ldmatrix)
static constexpr int TILE_BYTES = 128 * ROW_BYTES;   // 67584
static constexpr int SM_A_OFF  = 0;              // z1 tile
static constexpr int SM_B_OFF  = TILE_BYTES;     // z0*W tiles (x2)
static constexpr int SMEM_BYTES = 3 * TILE_BYTES;    // 202752

__device__ __forceinline__ uint32_t smem_u32(const void* p) {
    uint32_t a;
    asm("{ .reg .u64 t; cvta.to.shared.u64 t, %1; cvt.u32.u64 %0, t; }" : "=r"(a) : "l"(p));
    return a;
}

#define LDMATRIX_X4(r0, r1, r2, r3, addr)                                     \
    asm volatile("ldmatrix.sync.aligned.m8n8.x4.shared.b16 {%0,%1,%2,%3}, [%4];" \
                 : "=r"(r0), "=r"(r1), "=r"(r2), "=r"(r3) : "r"(addr))

#define MMA16816(c, a, b)                                                      \
    asm volatile("mma.sync.aligned.m16n8k16.row.col.f32.f16.f16.f32 "          \
                 "{%0,%1,%2,%3}, {%4,%5,%6,%7}, {%8,%9}, {%0,%1,%2,%3};"       \
                 : "+f"((c)[0]), "+f"((c)[1]), "+f"((c)[2]), "+f"((c)[3])      \
                 : "r"((a)[0]), "r"((a)[1]), "r"((a)[2]), "r"((a)[3]),         \
                   "r"((b)[0]), "r"((b)[1]))

__global__ void __launch_bounds__(NT, 1)
fc_fused_kernel(const float* __restrict__ z0, const float* __restrict__ z1,
                const float* __restrict__ W, const float* __restrict__ bias,
                float* __restrict__ out)
{
    extern __shared__ char smem[];
    const uint32_t smem_base = smem_u32(smem);
    const int tid = threadIdx.x;
    const int wid = tid >> 5;
    const int lid = tid & 31;

    const int n_tile = (int)(blockIdx.x >> 6);   // 0..7
    const int h0     = (int)(blockIdx.x & 63) << 1;
    const int n0     = n_tile << 7;

    // ---- Build B tiles: fp16(z0[n0:n0+128,:] * W[h]) into padded smem ----
    {
        const float4* z0t = reinterpret_cast<const float4*>(z0 + (size_t)n0 * 256);
        #pragma unroll 1
        for (int hh = 0; hh < 2; ++hh) {
            const float4* wr = reinterpret_cast<const float4*>(W + (size_t)(h0 + hh) * 256);
            char* sb = smem + SM_B_OFF + hh * TILE_BYTES;
            #pragma unroll
            for (int i = tid; i < 8192; i += NT) {
                int r = i >> 6, k4 = i & 63;
                float4 v = z0t[i];
                float4 w = wr[k4];
                union { __half2 h2[2]; uint2 u; } pk;
                pk.h2[0] = __floats2half2_rn(v.x * w.x, v.y * w.y);
                pk.h2[1] = __floats2half2_rn(v.z * w.z, v.w * w.w);
                *reinterpret_cast<uint2*>(sb + r * ROW_BYTES + k4 * 8) = pk.u;
            }
        }
    }

    // Warp tiling: 4(n) x 4(m) warps; each warp: 32 n x 32 m.
    const int wn  = wid & 3;    // n block (rows of MMA)
    const int wm2 = wid >> 2;   // m block (cols of MMA)

    // ldmatrix per-lane offset: rows (lane&15), column half (lane>>4)*16B
    const uint32_t lminc = (uint32_t)((lid & 15) * ROW_BYTES + (lid >> 4) * 16);
    // Operand A (B_h tile): two 16-n-row subtiles
    uint32_t a_addr[2];
    a_addr[0] = smem_base + SM_B_OFF + (uint32_t)((wn * 32) * ROW_BYTES) + lminc;
    a_addr[1] = a_addr[0] + 16 * ROW_BYTES;
    // Operand B (z1 tile): two 16-m-row subtiles (each = two n8 MMA tiles)
    uint32_t b_addr[2];
    b_addr[0] = smem_base + SM_A_OFF + (uint32_t)((wm2 * 32) * ROW_BYTES) + lminc;
    b_addr[1] = b_addr[0] + 16 * ROW_BYTES;

    const float bv[2] = { bias[h0], bias[h0 + 1] };

    #pragma unroll 1
    for (int mt = 0; mt < 8; ++mt) {
        const int m0 = mt << 7;

        // ---- Fill A tile: fp16(z1[m0:m0+128,:]) ----
        {
            const float4* z1t = reinterpret_cast<const float4*>(z1 + (size_t)m0 * 256);
            char* sa = smem + SM_A_OFF;
            #pragma unroll
            for (int i = tid; i < 8192; i += NT) {
                int r = i >> 6, k4 = i & 63;
                float4 v = z1t[i];
                union { __half2 h2[2]; uint2 u; } pk;
                pk.h2[0] = __floats2half2_rn(v.x, v.y);
                pk.h2[1] = __floats2half2_rn(v.z, v.w);
                *reinterpret_cast<uint2*>(sa + r * ROW_BYTES + k4 * 8) = pk.u;
            }
        }
        __syncthreads();

        #pragma unroll 1
        for (int hh = 0; hh < 2; ++hh) {
            const uint32_t hoff = (uint32_t)(hh * TILE_BYTES);

            float acc[2][4][4];
            #pragma unroll
            for (int mi = 0; mi < 2; ++mi)
                #pragma unroll
                for (int ni = 0; ni < 4; ++ni)
                    #pragma unroll
                    for (int q = 0; q < 4; ++q) acc[mi][ni][q] = 0.0f;

            #pragma unroll
            for (int ks = 0; ks < 16; ++ks) {
                const uint32_t ko = (uint32_t)(ks * 32);
                uint32_t a[2][4];
                LDMATRIX_X4(a[0][0], a[0][1], a[0][2], a[0][3], a_addr[0] + hoff + ko);
                LDMATRIX_X4(a[1][0], a[1][1], a[1][2], a[1][3], a_addr[1] + hoff + ko);
                uint32_t b[4][2];
                {
                    uint32_t r0, r1, r2, r3;
                    LDMATRIX_X4(r0, r1, r2, r3, b_addr[0] + ko);
                    b[0][0] = r0; b[1][0] = r1; b[0][1] = r2; b[1][1] = r3;
                    LDMATRIX_X4(r0, r1, r2, r3, b_addr[1] + ko);
                    b[2][0] = r0; b[3][0] = r1; b[2][1] = r2; b[3][1] = r3;
                }
                #pragma unroll
                for (int mi = 0; mi < 2; ++mi)
                    #pragma unroll
                    for (int ni = 0; ni < 4; ++ni)
                        MMA16816(acc[mi][ni], a[mi], b[ni]);
            }

            // ---- Epilogue: bias + LeakyReLU + float2 streaming stores ----
            const float bvv = bv[hh];
            const int r  = lid >> 2;
            const int c  = (lid & 3) << 1;
            float* ob = out + (((size_t)(h0 + hh)) << 20);
            #pragma unroll
            for (int mi = 0; mi < 2; ++mi) {
                const int ng = n0 + wn * 32 + mi * 16 + r;
                #pragma unroll
                for (int ni = 0; ni < 4; ++ni) {
                    const int mg = m0 + wm2 * 32 + ni * 8 + c;
                    float2 v0, v1;
                    v0.x = acc[mi][ni][0] + bvv; v0.y = acc[mi][ni][1] + bvv;
                    v1.x = acc[mi][ni][2] + bvv; v1.y = acc[mi][ni][3] + bvv;
                    v0.x = (v0.x >= 0.f) ? v0.x : 0.2f * v0.x;
                    v0.y = (v0.y >= 0.f) ? v0.y : 0.2f * v0.y;
                    v1.x = (v1.x >= 0.f) ? v1.x : 0.2f * v1.x;
                    v1.y = (v1.y >= 0.f) ? v1.y : 0.2f * v1.y;
                    __stcs(reinterpret_cast<float2*>(ob + (size_t)ng * 1024 + mg), v0);
                    __stcs(reinterpret_cast<float2*>(ob + (size_t)(ng + 8) * 1024 + mg), v1);
                }
            }
        }
        __syncthreads();   // A tile safe to overwrite next iteration
    }
}

extern "C" void kernel_launch(void* const* d_in, const int* in_sizes, int n_in,
                              void* d_out, int out_size) {
    const float* z0   = (const float*)d_in[0];   // (1, 1024, 256)
    const float* z1   = (const float*)d_in[1];   // (1, 1024, 256)
    const float* W    = (const float*)d_in[2];   // (128, 256)
    const float* bias = (const float*)d_in[3];   // (128,)
    float* out = (float*)d_out;                  // (1, 128, 1024, 1024)

    cudaFuncSetAttribute(fc_fused_kernel, cudaFuncAttributeMaxDynamicSharedMemorySize, SMEM_BYTES);
    fc_fused_kernel<<<512, NT, SMEM_BYTES>>>(z0, z1, W, bias, out);
}

// round 3
// speedup vs baseline: 1.1338x; 1.1338x over previous
#include <cuda_runtime.h>
#include <cuda_fp16.h>
#include <cstdint>
#include <cstddef>

// out[h,n,m] = LeakyReLU_{0.2}( sum_d z0[n,d]*z1[m,d]*W[h,d] + bias[h] )
// N=M=1024, D=256, H=128, fp32 in/out.
//
// Pipeline:
//  prep_z1 : z1  -> g_z1h  (fp16, per-128-row-tile XOR-swizzle baked)   512 KB
//  prep_y  : z0,W -> g_Yh  (fp16(z0*W[h]), same baked layout)            64 MB
//  main    : per CTA (h, n-tile): cp.async fills (B once, A double-buffered),
//            ldmatrix + mma.sync m16n8k16, fused bias+LeakyReLU epilogue.
//
// Warp tile: 32n x 64m, 8 warps (4n x 2m), NT=256, 1024 CTAs.

#define NT 256

static constexpr int TILE_BYTES = 65536;     // 128 rows x 512B (fp16 d=256), swizzle baked
static constexpr int SM_A0 = 0;
static constexpr int SM_A1 = 65536;
static constexpr int SM_B  = 131072;
static constexpr int SMEM_BYTES = 196608;    // 192 KB

__device__ uint4 g_Yh[128 * 8 * 4096];       // 64 MB  [h][ntile][4096 x 16B]
__device__ uint4 g_z1h[8 * 4096];            // 512 KB [mtile][4096 x 16B]

__device__ __forceinline__ uint32_t smem_u32(const void* p) {
    uint32_t a;
    asm("{ .reg .u64 t; cvta.to.shared.u64 t, %1; cvt.u32.u64 %0, t; }" : "=r"(a) : "l"(p));
    return a;
}

#define CP16(saddr, gptr)                                                     \
    asm volatile("cp.async.cg.shared.global [%0], [%1], 16;"                  \
                 :: "r"(saddr), "l"(gptr))
#define CP_COMMIT() asm volatile("cp.async.commit_group;" ::: "memory")
#define CP_WAIT(n)  asm volatile("cp.async.wait_group %0;" :: "n"(n) : "memory")

#define LDMATRIX_X4(r0, r1, r2, r3, addr)                                     \
    asm volatile("ldmatrix.sync.aligned.m8n8.x4.shared.b16 {%0,%1,%2,%3}, [%4];" \
                 : "=r"(r0), "=r"(r1), "=r"(r2), "=r"(r3) : "r"(addr))

#define MMA16816(c, a, b0, b1)                                                 \
    asm volatile("mma.sync.aligned.m16n8k16.row.col.f32.f16.f16.f32 "          \
                 "{%0,%1,%2,%3}, {%4,%5,%6,%7}, {%8,%9}, {%0,%1,%2,%3};"       \
                 : "+f"((c)[0]), "+f"((c)[1]), "+f"((c)[2]), "+f"((c)[3])      \
                 : "r"((a)[0]), "r"((a)[1]), "r"((a)[2]), "r"((a)[3]),         \
                   "r"(b0), "r"(b1))

// ---------------- pre-kernels: fp32 -> fp16, swizzle-baked ----------------
// Baked layout inside a 128-row tile: chunk(r, c16) at r*512 + (c16 ^ (r&7))*16.

__global__ void prep_z1_kernel(const float* __restrict__ z1) {
    const int wid = threadIdx.x >> 5, lid = threadIdx.x & 31;
    const int m = blockIdx.x * 8 + wid;                 // global m row
    const float4* src = reinterpret_cast<const float4*>(z1) + (size_t)m * 64 + lid * 2;
    float4 v0 = src[0], v1 = src[1];
    union { __half2 h2[4]; uint4 u; } pk;
    pk.h2[0] = __floats2half2_rn(v0.x, v0.y);
    pk.h2[1] = __floats2half2_rn(v0.z, v0.w);
    pk.h2[2] = __floats2half2_rn(v1.x, v1.y);
    pk.h2[3] = __floats2half2_rn(v1.z, v1.w);
    const int tile = m >> 7, r = m & 127;
    g_z1h[tile * 4096 + r * 32 + (lid ^ (r & 7))] = pk.u;
}

__global__ void prep_y_kernel(const float* __restrict__ z0, const float* __restrict__ W) {
    const int wid = threadIdx.x >> 5, lid = threadIdx.x & 31;
    const int h = blockIdx.x >> 7;
    const int n = (blockIdx.x & 127) * 8 + wid;
    const float4* zsrc = reinterpret_cast<const float4*>(z0) + (size_t)n * 64 + lid * 2;
    const float4* wsrc = reinterpret_cast<const float4*>(W)  + (size_t)h * 64 + lid * 2;
    float4 v0 = zsrc[0], v1 = zsrc[1];
    float4 w0 = wsrc[0], w1 = wsrc[1];
    union { __half2 h2[4]; uint4 u; } pk;
    pk.h2[0] = __floats2half2_rn(v0.x * w0.x, v0.y * w0.y);
    pk.h2[1] = __floats2half2_rn(v0.z * w0.z, v0.w * w0.w);
    pk.h2[2] = __floats2half2_rn(v1.x * w1.x, v1.y * w1.y);
    pk.h2[3] = __floats2half2_rn(v1.z * w1.z, v1.w * w1.w);
    const int tile = n >> 7, r = n & 127;
    g_Yh[(size_t)(h * 8 + tile) * 4096 + r * 32 + (lid ^ (r & 7))] = pk.u;
}

// ---------------- main kernel ----------------

__global__ void __launch_bounds__(NT, 1)
fc_main_kernel(const float* __restrict__ bias, float* __restrict__ out)
{
    extern __shared__ char smem[];
    const uint32_t smem_base = smem_u32(smem);
    const int tid = threadIdx.x;
    const int wid = tid >> 5;
    const int lid = tid & 31;

    const int h  = (int)(blockIdx.x & 127);
    const int nt = (int)(blockIdx.x >> 7);
    const int n0 = nt << 7;

    // Prologue fills: B (Yh tile for this (h, nt)), A0 (z1h m-tile 0)
    {
        const uint4* gB = g_Yh + (size_t)(h * 8 + nt) * 4096;
        #pragma unroll
        for (int i = 0; i < 16; ++i)
            CP16(smem_base + SM_B + (uint32_t)((tid + i * 256) * 16), gB + tid + i * 256);
        CP_COMMIT();
        const uint4* gA = g_z1h;
        #pragma unroll
        for (int i = 0; i < 16; ++i)
            CP16(smem_base + SM_A0 + (uint32_t)((tid + i * 256) * 16), gA + tid + i * 256);
        CP_COMMIT();
    }

    const float bv = bias[h];

    // Warp tiling: 4(n) x 2(m); warp tile 32n x 64m.
    const int wn = wid >> 1;           // 0..3
    const int wm = wid & 1;            // 0..1

    const uint32_t e   = (uint32_t)(lid & 7);
    const uint32_t hi  = (uint32_t)(lid >> 4);
    const uint32_t row = (uint32_t)(lid & 15);

    // lane bases (column term added per k-step)
    uint32_t a_base[2];                // operand A rows = n (from B tile)
    #pragma unroll
    for (int mi = 0; mi < 2; ++mi)
        a_base[mi] = smem_base + SM_B + (uint32_t)((wn * 32 + mi * 16 + row) * 512);
    uint32_t b_base[4];                // operand B rows = m (from A tile)
    #pragma unroll
    for (int u = 0; u < 4; ++u)
        b_base[u] = smem_base + (uint32_t)((wm * 64 + u * 16 + row) * 512);

    float acc[2][8][4];
    #pragma unroll
    for (int mi = 0; mi < 2; ++mi)
        #pragma unroll
        for (int j = 0; j < 8; ++j)
            #pragma unroll
            for (int q = 0; q < 4; ++q) acc[mi][j][q] = 0.0f;

    #pragma unroll 1
    for (int mt = 0; mt < 8; ++mt) {
        // Prefetch next A tile into the other buffer
        if (mt < 7) {
            const uint4* gA = g_z1h + (size_t)(mt + 1) * 4096;
            const uint32_t dst = smem_base + ((mt & 1) ? SM_A0 : SM_A1);
            #pragma unroll
            for (int i = 0; i < 16; ++i)
                CP16(dst + (uint32_t)((tid + i * 256) * 16), gA + tid + i * 256);
            CP_COMMIT();
            CP_WAIT(1);
        } else {
            CP_WAIT(0);
        }
        __syncthreads();

        const uint32_t abuf = (mt & 1) ? (uint32_t)SM_A1 : 0u;

        // k-loop, software-pipelined operand regs
        uint32_t ac[2][4], bc[4][4];
        {
            const uint32_t coff = (((0u * 2u + hi) ^ e) << 4);
            LDMATRIX_X4(ac[0][0], ac[0][1], ac[0][2], ac[0][3], a_base[0] + coff);
            LDMATRIX_X4(ac[1][0], ac[1][1], ac[1][2], ac[1][3], a_base[1] + coff);
            #pragma unroll
            for (int u = 0; u < 4; ++u)
                LDMATRIX_X4(bc[u][0], bc[u][1], bc[u][2], bc[u][3], b_base[u] + abuf + coff);
        }
        #pragma unroll
        for (int ks = 0; ks < 16; ++ks) {
            uint32_t an[2][4], bn[4][4];
            if (ks < 15) {
                const uint32_t coff = ((((uint32_t)(ks + 1) * 2u + hi) ^ e) << 4);
                LDMATRIX_X4(an[0][0], an[0][1], an[0][2], an[0][3], a_base[0] + coff);
                LDMATRIX_X4(an[1][0], an[1][1], an[1][2], an[1][3], a_base[1] + coff);
                #pragma unroll
                for (int u = 0; u < 4; ++u)
                    LDMATRIX_X4(bn[u][0], bn[u][1], bn[u][2], bn[u][3], b_base[u] + abuf + coff);
            }
            #pragma unroll
            for (int mi = 0; mi < 2; ++mi)
                #pragma unroll
                for (int u = 0; u < 4; ++u) {
                    MMA16816(acc[mi][2 * u + 0], ac[mi], bc[u][0], bc[u][2]);
                    MMA16816(acc[mi][2 * u + 1], ac[mi], bc[u][1], bc[u][3]);
                }
            if (ks < 15) {
                #pragma unroll
                for (int mi = 0; mi < 2; ++mi)
                    #pragma unroll
                    for (int q = 0; q < 4; ++q) ac[mi][q] = an[mi][q];
                #pragma unroll
                for (int u = 0; u < 4; ++u)
                    #pragma unroll
                    for (int q = 0; q < 4; ++q) bc[u][q] = bn[u][q];
            }
        }

        // Epilogue: bias + LeakyReLU + float2 streaming stores
        {
            const int m0 = mt << 7;
            const int rr = lid >> 2;
            const int cc = (lid & 3) << 1;
            float* ob = out + (((size_t)h) << 20);
            #pragma unroll
            for (int mi = 0; mi < 2; ++mi) {
                const int ng = n0 + wn * 32 + mi * 16 + rr;
                #pragma unroll
                for (int j = 0; j < 8; ++j) {
                    const int mg = m0 + wm * 64 + j * 8 + cc;
                    float2 v0, v1;
                    v0.x = acc[mi][j][0] + bv; v0.y = acc[mi][j][1] + bv;
                    v1.x = acc[mi][j][2] + bv; v1.y = acc[mi][j][3] + bv;
                    v0.x = (v0.x >= 0.f) ? v0.x : 0.2f * v0.x;
                    v0.y = (v0.y >= 0.f) ? v0.y : 0.2f * v0.y;
                    v1.x = (v1.x >= 0.f) ? v1.x : 0.2f * v1.x;
                    v1.y = (v1.y >= 0.f) ? v1.y : 0.2f * v1.y;
                    __stcs(reinterpret_cast<float2*>(ob + (size_t)ng * 1024 + mg), v0);
                    __stcs(reinterpret_cast<float2*>(ob + (size_t)(ng + 8) * 1024 + mg), v1);
                    acc[mi][j][0] = acc[mi][j][1] = acc[mi][j][2] = acc[mi][j][3] = 0.0f;
                }
            }
        }
        __syncthreads();   // all ldmatrix reads of this A buffer done before refill
    }
}

extern "C" void kernel_launch(void* const* d_in, const int* in_sizes, int n_in,
                              void* d_out, int out_size) {
    const float* z0   = (const float*)d_in[0];   // (1, 1024, 256)
    const float* z1   = (const float*)d_in[1];   // (1, 1024, 256)
    const float* W    = (const float*)d_in[2];   // (128, 256)
    const float* bias = (const float*)d_in[3];   // (128,)
    float* out = (float*)d_out;                  // (1, 128, 1024, 1024)

    prep_z1_kernel<<<128, 256>>>(z1);
    prep_y_kernel<<<16384, 256>>>(z0, W);

    cudaFuncSetAttribute(fc_main_kernel, cudaFuncAttributeMaxDynamicSharedMemorySize, SMEM_BYTES);
    fc_main_kernel<<<1024, NT, SMEM_BYTES>>>(bias, out);
}